// round 14
// baseline (speedup 1.0000x reference)
#include <cuda_runtime.h>
#include <math.h>

// MinDistLoss: out = min_{b,n,m} sqrt(max( xx[b,n] + yy[b,m] - 2*dot(v1[b,n],v2[b,m]), 0 ))
//
// FROZEN numeric scheme (bit-exact vs reference, rel_err = 0.0 since round 1):
//   xx  = (x0*x0 + x1*x1) + x2*x2                  (separate mul/add)
//   dot = fma(x2,y2, fma(x1,y1, x0*y0))            (ascending fma chain)
//   sq  = fma(-2, dot, xx+yy)
//
// R14: replicate points, not lookups. Each v2 point is scattered into ALL
// cells (width 2h) overlapping [y-h, y+h]^3 (<= 2 per dim -> <= 8 cells).
// Any pair with true dist <= h/1.05 then has cell(x) among the point's cells
// (0.05h margin >> fp rounding of the coordinate->cell maps), so the search
// does ONE cell lookup instead of 8 dependent lookup chains (k_search was
// 23us at issue=22% -- pure L2 pointer-chase latency).
// Replication only ADDS candidates; every candidate is evaluated with the
// exact frozen scheme -> min identical to brute force.

#define NB 16            // batches
#define HSIZE 8192       // hash buckets per batch (power of 2)
#define NPB 65536        // max scattered entries per batch (<= 8*6890)
#define FLT_MAX_BITS 0x7f7fffffu

__device__ int      g_offset[NB][HSIZE + 1];
__device__ float4   g_pts[NB][NPB];
__device__ float    g_inv2h[NB];
__device__ unsigned g_minbits = FLT_MAX_BITS;
__device__ unsigned g_tick    = 0;

// ---- frozen-scheme helpers ----
__device__ __forceinline__ float norm3(float a, float b, float c) {
    return __fadd_rn(__fadd_rn(__fmul_rn(a, a), __fmul_rn(b, b)), __fmul_rn(c, c));
}
__device__ __forceinline__ float sq_frozen(float x0, float x1, float x2, float xx,
                                           float y0, float y1, float y2, float yy) {
    float dot = __fmaf_rn(x2, y2, __fmaf_rn(x1, y1, __fmul_rn(x0, y0)));
    return __fmaf_rn(-2.0f, dot, __fadd_rn(xx, yy));
}
__device__ __forceinline__ unsigned cellhash(int cx, int cy, int cz) {
    unsigned h = (unsigned)cx * 73856093u ^ (unsigned)cy * 19349663u
               ^ (unsigned)cz * 83492791u;
    return h & (HSIZE - 1);
}
__device__ __forceinline__ float warp_min(float v) {
#pragma unroll
    for (int off = 16; off; off >>= 1)
        v = fminf(v, __shfl_xor_sync(0xffffffffu, v, off));
    return v;
}

// ---- 1) build: per-batch bound + replicated count/scan/scatter ----
__global__ __launch_bounds__(1024)
void k_build(const float* __restrict__ v1, const float* __restrict__ v2,
             int N, int M) {
    __shared__ int   scnt[HSIZE];     // counts -> cursors
    __shared__ int   wsum[32];
    __shared__ float sred[32];
    __shared__ float sh_h, sh_inv;
    const int b    = blockIdx.x;
    const int tid  = threadIdx.x;
    const int lane = tid & 31, wid = tid >> 5;
    const float* p1 = v1 + (size_t)b * N * 3;
    const float* p2 = v2 + (size_t)b * M * 3;

    // zero counts (disjoint from phase A state; barrier comes later anyway)
#pragma unroll
    for (int j = 0; j < HSIZE / 1024; j++) scnt[tid + j * 1024] = 0;

    // --- phase A: batch upper bound over 4 sampled pairings per v1 point ---
    float best = 3.4028235e38f;
    for (int n = tid; n < N; n += 1024) {
        float x0 = p1[n * 3 + 0], x1 = p1[n * 3 + 1], x2 = p1[n * 3 + 2];
        float xx = norm3(x0, x1, x2);
        const int offs[4] = {0, 1, 317, 4001};
#pragma unroll
        for (int k = 0; k < 4; k++) {
            int m = n + offs[k]; if (m >= M) m -= M; if (m >= M) m %= M;
            float y0 = p2[m * 3 + 0], y1 = p2[m * 3 + 1], y2 = p2[m * 3 + 2];
            float yy = norm3(y0, y1, y2);
            best = fminf(best, sq_frozen(x0, x1, x2, xx, y0, y1, y2, yy));
        }
    }
    best = warp_min(best);
    if (lane == 0) sred[wid] = best;
    __syncthreads();
    if (wid == 0) {
        float v = sred[lane];
        v = warp_min(v);
        if (lane == 0) {
            float usq = fmaxf(v, 0.0f);
            float h   = 1.05f * sqrtf(usq + 4e-3f);
            float inv = 1.0f / (2.0f * h);   // CELL SIZE = 2h
            g_inv2h[b] = inv; sh_h = h; sh_inv = inv;
        }
    }
    __syncthreads();
    const float h   = sh_h;
    const float inv = sh_inv;

    // --- count: each point into all cells overlapping [y-h, y+h]^3 ---
    for (int m = tid; m < M; m += 1024) {
        float y0 = p2[m * 3 + 0], y1 = p2[m * 3 + 1], y2 = p2[m * 3 + 2];
        int cx0 = __float2int_rd((y0 - h) * inv), cx1 = __float2int_rd((y0 + h) * inv);
        int cy0 = __float2int_rd((y1 - h) * inv), cy1 = __float2int_rd((y1 + h) * inv);
        int cz0 = __float2int_rd((y2 - h) * inv), cz1 = __float2int_rd((y2 + h) * inv);
        for (int cz = cz0; cz <= cz1; cz++)
            for (int cy = cy0; cy <= cy1; cy++)
                for (int cx = cx0; cx <= cx1; cx++)
                    atomicAdd(&scnt[cellhash(cx, cy, cz)], 1);
    }
    __syncthreads();

    // --- exclusive scan of 8192 counts (8/thread + shuffle hierarchy) ---
    const int base = tid * 8;
    int c[8], s = 0;
#pragma unroll
    for (int j = 0; j < 8; j++) { c[j] = scnt[base + j]; s += c[j]; }
    int incl = s;
#pragma unroll
    for (int off = 1; off < 32; off <<= 1) {
        int v = __shfl_up_sync(0xffffffffu, incl, off);
        if (lane >= off) incl += v;
    }
    if (lane == 31) wsum[wid] = incl;
    __syncthreads();
    if (wid == 0) {
        int v = wsum[lane], iv = v;
#pragma unroll
        for (int off = 1; off < 32; off <<= 1) {
            int t = __shfl_up_sync(0xffffffffu, iv, off);
            if (lane >= off) iv += t;
        }
        wsum[lane] = iv - v;
    }
    __syncthreads();
    int run = (incl - s) + wsum[wid];
#pragma unroll
    for (int j = 0; j < 8; j++) {
        g_offset[b][base + j] = run;
        scnt[base + j] = run;            // counts become cursors
        run += c[j];
    }
    if (tid == 1023) g_offset[b][HSIZE] = run;
    __syncthreads();

    // --- scatter with replication (frozen norm in .w) ---
    for (int m = tid; m < M; m += 1024) {
        float y0 = p2[m * 3 + 0], y1 = p2[m * 3 + 1], y2 = p2[m * 3 + 2];
        float4 rec = make_float4(y0, y1, y2, norm3(y0, y1, y2));
        int cx0 = __float2int_rd((y0 - h) * inv), cx1 = __float2int_rd((y0 + h) * inv);
        int cy0 = __float2int_rd((y1 - h) * inv), cy1 = __float2int_rd((y1 + h) * inv);
        int cz0 = __float2int_rd((y2 - h) * inv), cz1 = __float2int_rd((y2 + h) * inv);
        for (int cz = cz0; cz <= cz1; cz++)
            for (int cy = cy0; cy <= cy1; cy++)
                for (int cx = cx0; cx <= cx1; cx++) {
                    int pos = atomicAdd(&scnt[cellhash(cx, cy, cz)], 1);
                    g_pts[b][pos] = rec;
                }
    }
}

// ---- 2) search (ONE cell) + fused finalize ----
__global__ void k_search(const float* __restrict__ v1, int N, int nblocks,
                         float* __restrict__ out) {
    int idx = blockIdx.x * blockDim.x + threadIdx.x;
    float best = 3.4028235e38f;
    if (idx < NB * N) {
        int b = idx / N, n = idx % N;
        const float* p = v1 + ((size_t)b * N + n) * 3;
        float x0 = p[0], x1 = p[1], x2 = p[2];
        float xx  = norm3(x0, x1, x2);
        float inv = g_inv2h[b];
        unsigned hsh = cellhash(__float2int_rd(x0 * inv),
                                __float2int_rd(x1 * inv),
                                __float2int_rd(x2 * inv));
        int s = g_offset[b][hsh];
        int e = g_offset[b][hsh + 1];
        for (int i = s; i < e; i++) {
            float4 q = g_pts[b][i];
            best = fminf(best, sq_frozen(x0, x1, x2, xx, q.x, q.y, q.z, q.w));
        }
    }
    best = warp_min(best);
    __shared__ float wmin[8];
    int tid = threadIdx.x;
    if ((tid & 31) == 0) wmin[tid >> 5] = best;
    __syncthreads();
    if (tid == 0) {
        float r = wmin[0];
#pragma unroll
        for (int w = 1; w < 8; w++) r = fminf(r, wmin[w]);
        atomicMin(&g_minbits, __float_as_uint(fmaxf(r, 0.0f)));
        __threadfence();
        unsigned ticket = atomicAdd(&g_tick, 1);
        if (ticket == (unsigned)(nblocks - 1)) {
            unsigned bits = atomicExch(&g_minbits, FLT_MAX_BITS);
            atomicExch(&g_tick, 0u);
            out[0] = sqrtf(__uint_as_float(bits));
        }
    }
}

extern "C" void kernel_launch(void* const* d_in, const int* in_sizes, int n_in,
                              void* d_out, int out_size) {
    const float* v1 = (const float*)d_in[0];
    const float* v2 = (const float*)d_in[1];
    float* out = (float*)d_out;

    const int B = NB;
    const int N = in_sizes[0] / (B * 3);
    const int M = in_sizes[1] / (B * 3);

    int sblocks = (B * N + 255) / 256;
    k_build<<<NB, 1024>>>(v1, v2, N, M);
    k_search<<<sblocks, 256>>>(v1, N, sblocks, out);
}

// round 15
// speedup vs baseline: 1.2131x; 1.2131x over previous
#include <cuda_runtime.h>
#include <math.h>

// MinDistLoss: out = min_{b,n,m} sqrt(max( xx[b,n] + yy[b,m] - 2*dot(v1[b,n],v2[b,m]), 0 ))
//
// FROZEN numeric scheme (bit-exact vs reference, rel_err = 0.0 since round 1):
//   xx  = (x0*x0 + x1*x1) + x2*x2                  (separate mul/add)
//   dot = fma(x2,y2, fma(x1,y1, x0*y0))            (ascending fma chain)
//   sq  = fma(-2, dot, xx+yy)
//
// R15 = R13 (best structure) + batched independent cell lookups.
//  k_build (16 blocks, 1/batch): per-batch U_b^2 over 4 sampled pairings ->
//    h_b = 1.05*sqrt(U_b^2+4e-3), cells of width 2h; SMEM counts ->
//    warp-shuffle scan -> scatter float4(y, yy). Cell table is int2(start,end)
//    so the search needs ONE 8B load per cell.
//  k_search: all 8 cell hashes computed first (ALU), then 8 INDEPENDENT int2
//    loads (MLP=8, one L2 round instead of 8 serialized chains), then exact
//    frozen evals; last-block ticket writes sqrt(min) + resets state.
// Hash collisions / duplicate cells only ADD candidates; every candidate is
// evaluated with the exact frozen scheme -> min identical to brute force.

#define NB 16            // batches
#define HSIZE 8192       // hash buckets per batch (power of 2)
#define NPB 8192         // max points per batch
#define FLT_MAX_BITS 0x7f7fffffu

__device__ int2     g_cell[NB][HSIZE];   // (start, end) per bucket
__device__ float4   g_pts[NB][NPB];
__device__ float    g_h[NB];
__device__ float    g_inv2h[NB];
__device__ unsigned g_minbits = FLT_MAX_BITS;
__device__ unsigned g_tick    = 0;

// ---- frozen-scheme helpers ----
__device__ __forceinline__ float norm3(float a, float b, float c) {
    return __fadd_rn(__fadd_rn(__fmul_rn(a, a), __fmul_rn(b, b)), __fmul_rn(c, c));
}
__device__ __forceinline__ float sq_frozen(float x0, float x1, float x2, float xx,
                                           float y0, float y1, float y2, float yy) {
    float dot = __fmaf_rn(x2, y2, __fmaf_rn(x1, y1, __fmul_rn(x0, y0)));
    return __fmaf_rn(-2.0f, dot, __fadd_rn(xx, yy));
}
__device__ __forceinline__ unsigned cellhash(int cx, int cy, int cz) {
    unsigned h = (unsigned)cx * 73856093u ^ (unsigned)cy * 19349663u
               ^ (unsigned)cz * 83492791u;
    return h & (HSIZE - 1);
}
__device__ __forceinline__ float warp_min(float v) {
#pragma unroll
    for (int off = 16; off; off >>= 1)
        v = fminf(v, __shfl_xor_sync(0xffffffffu, v, off));
    return v;
}

// ---- 1) build: per-batch upper bound + count + scan + scatter ----
__global__ __launch_bounds__(1024)
void k_build(const float* __restrict__ v1, const float* __restrict__ v2,
             int N, int M) {
    __shared__ int   scnt[HSIZE];     // counts -> cursors
    __shared__ int   wsum[32];
    __shared__ float sred[32];
    __shared__ float sh_inv;
    const int b    = blockIdx.x;
    const int tid  = threadIdx.x;
    const int lane = tid & 31, wid = tid >> 5;
    const float* p1 = v1 + (size_t)b * N * 3;
    const float* p2 = v2 + (size_t)b * M * 3;

    // zero counts
#pragma unroll
    for (int j = 0; j < HSIZE / 1024; j++) scnt[tid + j * 1024] = 0;

    // --- phase A: batch upper bound over 4 sampled pairings per v1 point ---
    float best = 3.4028235e38f;
    for (int n = tid; n < N; n += 1024) {
        float x0 = p1[n * 3 + 0], x1 = p1[n * 3 + 1], x2 = p1[n * 3 + 2];
        float xx = norm3(x0, x1, x2);
        const int offs[4] = {0, 1, 317, 4001};
#pragma unroll
        for (int k = 0; k < 4; k++) {
            int m = n + offs[k]; if (m >= M) m -= M; if (m >= M) m %= M;
            float y0 = p2[m * 3 + 0], y1 = p2[m * 3 + 1], y2 = p2[m * 3 + 2];
            float yy = norm3(y0, y1, y2);
            best = fminf(best, sq_frozen(x0, x1, x2, xx, y0, y1, y2, yy));
        }
    }
    best = warp_min(best);
    if (lane == 0) sred[wid] = best;
    __syncthreads();
    if (wid == 0) {
        float v = sred[lane];
        v = warp_min(v);
        if (lane == 0) {
            float usq = fmaxf(v, 0.0f);
            float h   = 1.05f * sqrtf(usq + 4e-3f);
            float inv = 1.0f / (2.0f * h);   // CELL SIZE = 2h
            g_h[b] = h; g_inv2h[b] = inv; sh_inv = inv;
        }
    }
    __syncthreads();
    const float inv = sh_inv;

    // --- count (save hashes; <= 7 pts/thread at M=6890) ---
    unsigned hsave[8];
    int      npt = 0;
    for (int m = tid; m < M; m += 1024) {
        float y0 = p2[m * 3 + 0], y1 = p2[m * 3 + 1], y2 = p2[m * 3 + 2];
        unsigned h = cellhash(__float2int_rd(y0 * inv),
                              __float2int_rd(y1 * inv),
                              __float2int_rd(y2 * inv));
        hsave[npt++] = h;
        atomicAdd(&scnt[h], 1);
    }
    __syncthreads();

    // --- exclusive scan of 8192 counts (8/thread + shuffle hierarchy) ---
    const int base = tid * 8;
    int c[8], s = 0;
#pragma unroll
    for (int j = 0; j < 8; j++) { c[j] = scnt[base + j]; s += c[j]; }
    int incl = s;
#pragma unroll
    for (int off = 1; off < 32; off <<= 1) {
        int v = __shfl_up_sync(0xffffffffu, incl, off);
        if (lane >= off) incl += v;
    }
    if (lane == 31) wsum[wid] = incl;
    __syncthreads();
    if (wid == 0) {
        int v = wsum[lane], iv = v;
#pragma unroll
        for (int off = 1; off < 32; off <<= 1) {
            int t = __shfl_up_sync(0xffffffffu, iv, off);
            if (lane >= off) iv += t;
        }
        wsum[lane] = iv - v;
    }
    __syncthreads();
    int run = (incl - s) + wsum[wid];
#pragma unroll
    for (int j = 0; j < 8; j++) {
        g_cell[b][base + j] = make_int2(run, run + c[j]);   // (start, end)
        scnt[base + j] = run;            // counts become cursors
        run += c[j];
    }
    __syncthreads();

    // --- scatter (coords L1-hot), frozen norm in .w ---
    int k = 0;
    for (int m = tid; m < M; m += 1024) {
        float y0 = p2[m * 3 + 0], y1 = p2[m * 3 + 1], y2 = p2[m * 3 + 2];
        int pos = atomicAdd(&scnt[hsave[k++]], 1);
        g_pts[b][pos] = make_float4(y0, y1, y2, norm3(y0, y1, y2));
    }
}

// ---- 2) search: 8 batched cell lookups + fused finalize ----
__global__ void k_search(const float* __restrict__ v1, int N, int nblocks,
                         float* __restrict__ out) {
    int idx = blockIdx.x * blockDim.x + threadIdx.x;
    float best = 3.4028235e38f;
    if (idx < NB * N) {
        int b = idx / N, n = idx % N;
        const float* p = v1 + ((size_t)b * N + n) * 3;
        float x0 = p[0], x1 = p[1], x2 = p[2];
        float xx  = norm3(x0, x1, x2);
        float h   = g_h[b];
        float inv = g_inv2h[b];
        int cx[2], cy[2], cz[2];
        cx[0] = __float2int_rd((x0 - h) * inv); cx[1] = __float2int_rd((x0 + h) * inv);
        cy[0] = __float2int_rd((x1 - h) * inv); cy[1] = __float2int_rd((x1 + h) * inv);
        cz[0] = __float2int_rd((x2 - h) * inv); cz[1] = __float2int_rd((x2 + h) * inv);

        // all 8 hashes (ALU only), then 8 INDEPENDENT int2 loads (MLP=8)
        unsigned hh[8];
#pragma unroll
        for (int k = 0; k < 8; k++)
            hh[k] = cellhash(cx[k & 1], cy[(k >> 1) & 1], cz[k >> 2]);
        int2 se[8];
#pragma unroll
        for (int k = 0; k < 8; k++) se[k] = g_cell[b][hh[k]];

#pragma unroll
        for (int k = 0; k < 8; k++) {
            for (int i = se[k].x; i < se[k].y; i++) {
                float4 q = g_pts[b][i];
                best = fminf(best, sq_frozen(x0, x1, x2, xx, q.x, q.y, q.z, q.w));
            }
        }
    }
    best = warp_min(best);
    __shared__ float wmin[8];
    int tid = threadIdx.x;
    if ((tid & 31) == 0) wmin[tid >> 5] = best;
    __syncthreads();
    if (tid == 0) {
        float r = wmin[0];
#pragma unroll
        for (int w = 1; w < 8; w++) r = fminf(r, wmin[w]);
        atomicMin(&g_minbits, __float_as_uint(fmaxf(r, 0.0f)));
        __threadfence();
        unsigned ticket = atomicAdd(&g_tick, 1);
        if (ticket == (unsigned)(nblocks - 1)) {
            unsigned bits = atomicExch(&g_minbits, FLT_MAX_BITS);
            atomicExch(&g_tick, 0u);
            out[0] = sqrtf(__uint_as_float(bits));
        }
    }
}

extern "C" void kernel_launch(void* const* d_in, const int* in_sizes, int n_in,
                              void* d_out, int out_size) {
    const float* v1 = (const float*)d_in[0];
    const float* v2 = (const float*)d_in[1];
    float* out = (float*)d_out;

    const int B = NB;
    const int N = in_sizes[0] / (B * 3);
    const int M = in_sizes[1] / (B * 3);

    int sblocks = (B * N + 255) / 256;
    k_build<<<NB, 1024>>>(v1, v2, N, M);
    k_search<<<sblocks, 256>>>(v1, N, sblocks, out);
}

// round 16
// speedup vs baseline: 1.8683x; 1.5401x over previous
#include <cuda_runtime.h>
#include <math.h>

// MinDistLoss: out = min_{b,n,m} sqrt(max( xx[b,n] + yy[b,m] - 2*dot(v1[b,n],v2[b,m]), 0 ))
//
// FROZEN numeric scheme (bit-exact vs reference, rel_err = 0.0 since round 1):
//   xx  = (x0*x0 + x1*x1) + x2*x2                  (separate mul/add)
//   dot = fma(x2,y2, fma(x1,y1, x0*y0))            (ascending fma chain)
//   sq  = fma(-2, dot, xx+yy)
//
// R16 = R13 (best, 43.5us) + 4-way query split in k_search.
// R13's search was latency-bound at occ 31%/issue 22%: only 110k threads, each
// serially chasing 8 cell lookup chains. Now 4 threads per query (2 cells
// each): 4x threads, 1/4 the per-thread dependent chain. (R14/R15 lessons:
// don't move work into the 16-block build; don't batch lookups into big
// register arrays.) Same candidate set + same frozen evals -> bit-exact.

#define NB 16            // batches
#define HSIZE 8192       // hash buckets per batch (power of 2)
#define NPB 8192         // max points per batch
#define SPLIT 4          // threads per query
#define FLT_MAX_BITS 0x7f7fffffu

__device__ int      g_offset[NB][HSIZE + 1];
__device__ float4   g_pts[NB][NPB];
__device__ float    g_h[NB];
__device__ float    g_inv2h[NB];
__device__ unsigned g_minbits = FLT_MAX_BITS;
__device__ unsigned g_tick    = 0;

// ---- frozen-scheme helpers ----
__device__ __forceinline__ float norm3(float a, float b, float c) {
    return __fadd_rn(__fadd_rn(__fmul_rn(a, a), __fmul_rn(b, b)), __fmul_rn(c, c));
}
__device__ __forceinline__ float sq_frozen(float x0, float x1, float x2, float xx,
                                           float y0, float y1, float y2, float yy) {
    float dot = __fmaf_rn(x2, y2, __fmaf_rn(x1, y1, __fmul_rn(x0, y0)));
    return __fmaf_rn(-2.0f, dot, __fadd_rn(xx, yy));
}
__device__ __forceinline__ unsigned cellhash(int cx, int cy, int cz) {
    unsigned h = (unsigned)cx * 73856093u ^ (unsigned)cy * 19349663u
               ^ (unsigned)cz * 83492791u;
    return h & (HSIZE - 1);
}
__device__ __forceinline__ float warp_min(float v) {
#pragma unroll
    for (int off = 16; off; off >>= 1)
        v = fminf(v, __shfl_xor_sync(0xffffffffu, v, off));
    return v;
}

// ---- 1) build: per-batch upper bound + count + scan + scatter (== R13) ----
__global__ __launch_bounds__(1024)
void k_build(const float* __restrict__ v1, const float* __restrict__ v2,
             int N, int M) {
    __shared__ int   scnt[HSIZE];     // counts -> cursors
    __shared__ int   wsum[32];
    __shared__ float sred[32];
    __shared__ float sh_inv;
    const int b    = blockIdx.x;
    const int tid  = threadIdx.x;
    const int lane = tid & 31, wid = tid >> 5;
    const float* p1 = v1 + (size_t)b * N * 3;
    const float* p2 = v2 + (size_t)b * M * 3;

    // zero counts
#pragma unroll
    for (int j = 0; j < HSIZE / 1024; j++) scnt[tid + j * 1024] = 0;

    // --- phase A: batch upper bound over 4 sampled pairings per v1 point ---
    float best = 3.4028235e38f;
    for (int n = tid; n < N; n += 1024) {
        float x0 = p1[n * 3 + 0], x1 = p1[n * 3 + 1], x2 = p1[n * 3 + 2];
        float xx = norm3(x0, x1, x2);
        const int offs[4] = {0, 1, 317, 4001};
#pragma unroll
        for (int k = 0; k < 4; k++) {
            int m = n + offs[k]; if (m >= M) m -= M; if (m >= M) m %= M;
            float y0 = p2[m * 3 + 0], y1 = p2[m * 3 + 1], y2 = p2[m * 3 + 2];
            float yy = norm3(y0, y1, y2);
            best = fminf(best, sq_frozen(x0, x1, x2, xx, y0, y1, y2, yy));
        }
    }
    best = warp_min(best);
    if (lane == 0) sred[wid] = best;
    __syncthreads();
    if (wid == 0) {
        float v = sred[lane];
        v = warp_min(v);
        if (lane == 0) {
            float usq = fmaxf(v, 0.0f);
            float h   = 1.05f * sqrtf(usq + 4e-3f);
            float inv = 1.0f / (2.0f * h);   // CELL SIZE = 2h
            g_h[b] = h; g_inv2h[b] = inv; sh_inv = inv;
        }
    }
    __syncthreads();
    const float inv = sh_inv;

    // --- count (save hashes; <= 7 pts/thread at M=6890) ---
    unsigned hsave[8];
    int      npt = 0;
    for (int m = tid; m < M; m += 1024) {
        float y0 = p2[m * 3 + 0], y1 = p2[m * 3 + 1], y2 = p2[m * 3 + 2];
        unsigned h = cellhash(__float2int_rd(y0 * inv),
                              __float2int_rd(y1 * inv),
                              __float2int_rd(y2 * inv));
        hsave[npt++] = h;
        atomicAdd(&scnt[h], 1);
    }
    __syncthreads();

    // --- exclusive scan of 8192 counts (8/thread + shuffle hierarchy) ---
    const int base = tid * 8;
    int c[8], s = 0;
#pragma unroll
    for (int j = 0; j < 8; j++) { c[j] = scnt[base + j]; s += c[j]; }
    int incl = s;
#pragma unroll
    for (int off = 1; off < 32; off <<= 1) {
        int v = __shfl_up_sync(0xffffffffu, incl, off);
        if (lane >= off) incl += v;
    }
    if (lane == 31) wsum[wid] = incl;
    __syncthreads();
    if (wid == 0) {
        int v = wsum[lane], iv = v;
#pragma unroll
        for (int off = 1; off < 32; off <<= 1) {
            int t = __shfl_up_sync(0xffffffffu, iv, off);
            if (lane >= off) iv += t;
        }
        wsum[lane] = iv - v;
    }
    __syncthreads();
    int run = (incl - s) + wsum[wid];
#pragma unroll
    for (int j = 0; j < 8; j++) {
        g_offset[b][base + j] = run;
        scnt[base + j] = run;            // counts become cursors
        run += c[j];
    }
    if (tid == 1023) g_offset[b][HSIZE] = run;
    __syncthreads();

    // --- scatter (coords L1-hot), frozen norm in .w ---
    int k = 0;
    for (int m = tid; m < M; m += 1024) {
        float y0 = p2[m * 3 + 0], y1 = p2[m * 3 + 1], y2 = p2[m * 3 + 2];
        int pos = atomicAdd(&scnt[hsave[k++]], 1);
        g_pts[b][pos] = make_float4(y0, y1, y2, norm3(y0, y1, y2));
    }
}

// ---- 2) search: 4 threads per query, 2 cells each; fused finalize ----
__global__ void k_search(const float* __restrict__ v1, int N, int nblocks,
                         float* __restrict__ out) {
    int idx = blockIdx.x * blockDim.x + threadIdx.x;
    float best = 3.4028235e38f;
    if (idx < NB * N * SPLIT) {
        int q    = idx >> 2;        // query index
        int part = idx & 3;         // cells 2*part, 2*part+1
        int b = q / N, n = q % N;
        const float* p = v1 + ((size_t)b * N + n) * 3;
        float x0 = p[0], x1 = p[1], x2 = p[2];
        float xx  = norm3(x0, x1, x2);
        float h   = g_h[b];
        float inv = g_inv2h[b];
        int cx[2], cy[2], cz[2];
        cx[0] = __float2int_rd((x0 - h) * inv); cx[1] = __float2int_rd((x0 + h) * inv);
        cy[0] = __float2int_rd((x1 - h) * inv); cy[1] = __float2int_rd((x1 + h) * inv);
        cz[0] = __float2int_rd((x2 - h) * inv); cz[1] = __float2int_rd((x2 + h) * inv);
#pragma unroll
        for (int kk = 0; kk < 2; kk++) {
            int k = part * 2 + kk;
            unsigned hsh = cellhash(cx[k & 1], cy[(k >> 1) & 1], cz[k >> 2]);
            int s = g_offset[b][hsh];
            int e = g_offset[b][hsh + 1];
            for (int i = s; i < e; i++) {
                float4 qq = g_pts[b][i];
                best = fminf(best, sq_frozen(x0, x1, x2, xx,
                                             qq.x, qq.y, qq.z, qq.w));
            }
        }
    }
    best = warp_min(best);
    __shared__ float wmin[8];
    int tid = threadIdx.x;
    if ((tid & 31) == 0) wmin[tid >> 5] = best;
    __syncthreads();
    if (tid == 0) {
        float r = wmin[0];
#pragma unroll
        for (int w = 1; w < 8; w++) r = fminf(r, wmin[w]);
        atomicMin(&g_minbits, __float_as_uint(fmaxf(r, 0.0f)));
        __threadfence();
        unsigned ticket = atomicAdd(&g_tick, 1);
        if (ticket == (unsigned)(nblocks - 1)) {
            unsigned bits = atomicExch(&g_minbits, FLT_MAX_BITS);
            atomicExch(&g_tick, 0u);
            out[0] = sqrtf(__uint_as_float(bits));
        }
    }
}

extern "C" void kernel_launch(void* const* d_in, const int* in_sizes, int n_in,
                              void* d_out, int out_size) {
    const float* v1 = (const float*)d_in[0];
    const float* v2 = (const float*)d_in[1];
    float* out = (float*)d_out;

    const int B = NB;
    const int N = in_sizes[0] / (B * 3);
    const int M = in_sizes[1] / (B * 3);

    int sblocks = (B * N * SPLIT + 255) / 256;
    k_build<<<NB, 1024>>>(v1, v2, N, M);
    k_search<<<sblocks, 256>>>(v1, N, sblocks, out);
}